// round 9
// baseline (speedup 1.0000x reference)
#include <cuda_runtime.h>
#include <cuda_bf16.h>

#define HWD  56
#define NBLK 1568   // 32 images * 49 spatial blocks
#define NT   512    // threads per CTA (16 warps)

// ---------------- device scratch ----------------
__device__ __align__(16) __nv_bfloat16 g_W1B[256 * 1024]; // [K=256][N=1024]
__device__ __align__(16) __nv_bfloat16 g_W2B[1024 * 256]; // [K=1024][N=256]
__device__ int g_nact;
__device__ int g_act[NBLK];

__global__ void convert_weights(const float* __restrict__ w1,
                                const float* __restrict__ w2) {
    int id = blockIdx.x * blockDim.x + threadIdx.x;
    if (id == 0) g_nact = 0;
    if (id < 256 * 1024) {
        g_W1B[id] = __float2bfloat16(w1[id]);
        g_W2B[id] = __float2bfloat16(w2[id]);
    }
}

__global__ void build_lists(const int* __restrict__ mask) {
    int id = blockIdx.x * blockDim.x + threadIdx.x;
    bool act = (id < NBLK) && (mask[id] != 0);
    unsigned bal = __ballot_sync(0xFFFFFFFFu, act);
    if (act) {
        int lane = threadIdx.x & 31;
        int ldr  = __ffs(bal) - 1;
        int base = 0;
        if (lane == ldr) base = atomicAdd(&g_nact, __popc(bal));
        base = __shfl_sync(bal, base, ldr);
        int rank = __popc(bal & ((1u << lane) - 1));
        g_act[base + rank] = id;
    }
}

__global__ void copy_kernel(const float* __restrict__ x,
                            const int* __restrict__ mask,
                            float* __restrict__ out) {
    int blk = blockIdx.x;
    if (mask[blk] != 0) return;
    int b = blk / 49, s = blk % 49;
    int h0 = (s / 7) * 8, w0 = (s % 7) * 8;
    const float* xb = x   + (size_t)b * 256 * HWD * HWD;
    float*       ob = out + (size_t)b * 256 * HWD * HWD;
    for (int i = threadIdx.x; i < 4096; i += 256) {
        int c = i >> 4, sub = i & 15;
        int rr = sub >> 1, half = sub & 1;
        size_t g = (size_t)(c * HWD + h0 + rr) * HWD + w0;
        ((float4*)(ob + g))[half] = ((const float4*)(xb + g))[half];
    }
}

// ---------------- smem layout (bytes) ----------------
// Y    : bf16 [128][264] = 67584
// Zacc : bf16 [128][258] = 66048  (alias: dws f32 256*49 = 50176 during conv)
// W1c  : bf16 [256][72]  = 36864  (alias with W2c/Hc: conv patch f32 32*14*40 = 71680)
// W2c  : bf16 [64][264]  = 33792
// Hc   : bf16 [128][72]  = 18432
#define Y_OFF      0
#define Y_STRIDE   264
#define ZACC_OFF   67584
#define Z_STRIDE   258
#define W1C_OFF    133632
#define W1C_STRIDE 72
#define W2C_OFF    170496
#define W2C_STRIDE 264
#define HC_OFF     204288
#define HC_STRIDE  72
#define B1C_OFF    222720
#define DWB_OFF    222976
#define LNW_OFF    224000
#define LNB_OFF    225024
#define RS_OFF     226048
#define RQ_OFF     228096
#define SMEM_TOTAL 230144

__device__ __forceinline__ unsigned smem_u32(const void* p) {
    return (unsigned)__cvta_generic_to_shared(p);
}
__device__ __forceinline__ void ldsm4(unsigned r[4], unsigned addr) {
    asm volatile("ldmatrix.sync.aligned.m8n8.x4.shared.b16 {%0,%1,%2,%3}, [%4];"
                 : "=r"(r[0]), "=r"(r[1]), "=r"(r[2]), "=r"(r[3]) : "r"(addr));
}
__device__ __forceinline__ void ldsm4t(unsigned r[4], unsigned addr) {
    asm volatile("ldmatrix.sync.aligned.m8n8.x4.trans.shared.b16 {%0,%1,%2,%3}, [%4];"
                 : "=r"(r[0]), "=r"(r[1]), "=r"(r[2]), "=r"(r[3]) : "r"(addr));
}
__device__ __forceinline__ void mma16816(float d[4], const unsigned a[4],
                                         unsigned b0, unsigned b1) {
    asm volatile(
        "mma.sync.aligned.m16n8k16.row.col.f32.bf16.bf16.f32 "
        "{%0,%1,%2,%3}, {%4,%5,%6,%7}, {%8,%9}, {%0,%1,%2,%3};"
        : "+f"(d[0]), "+f"(d[1]), "+f"(d[2]), "+f"(d[3])
        : "r"(a[0]), "r"(a[1]), "r"(a[2]), "r"(a[3]), "r"(b0), "r"(b1));
}
__device__ __forceinline__ float gelu_f(float v) {
    float u = 0.7978845608028654f * (v + 0.044715f * v * v * v);
    float th;
    asm("tanh.approx.f32 %0, %1;" : "=f"(th) : "f"(u));
    return 0.5f * v * (1.0f + th);
}

__global__ __launch_bounds__(NT, 1)
void block_kernel(const float* __restrict__ x,
                  const float* __restrict__ dw_w, const float* __restrict__ dw_b,
                  const float* __restrict__ ln_w, const float* __restrict__ ln_b,
                  const float* __restrict__ b1, const float* __restrict__ b2,
                  const float* __restrict__ gamma, float* __restrict__ out) {
    extern __shared__ char sm[];
    const int t = threadIdx.x;
    const int j = blockIdx.x;
    const int i0 = 2 * j;
    const int nact = g_nact;
    if (i0 >= nact) return;
    const bool hasB = (i0 + 1 < nact);
    const int blkA = g_act[i0];
    const int blkB = hasB ? g_act[i0 + 1] : blkA;

    const int bA = blkA / 49, sA = blkA % 49;
    const int bB = blkB / 49, sB = blkB % 49;
    const int h0A = (sA / 7) * 8, w0A = (sA % 7) * 8;
    const int h0B = (sB / 7) * 8, w0B = (sB % 7) * 8;
    const float* xbA = x   + (size_t)bA * 256 * HWD * HWD;
    const float* xbB = x   + (size_t)bB * 256 * HWD * HWD;
    float*       obA = out + (size_t)bA * 256 * HWD * HWD;
    float*       obB = out + (size_t)bB * 256 * HWD * HWD;

    __nv_bfloat16* Ys   = (__nv_bfloat16*)(sm + Y_OFF);
    __nv_bfloat16* Zacc = (__nv_bfloat16*)(sm + ZACC_OFF);
    float* dws   = (float*)(sm + ZACC_OFF);   // alias (conv phase only)
    float* patch = (float*)(sm + W1C_OFF);    // alias (conv phase only), 71680 B
    float* b1c   = (float*)(sm + B1C_OFF);
    float* dwb_s = (float*)(sm + DWB_OFF);
    float* lnw_s = (float*)(sm + LNW_OFF);
    float* lnb_s = (float*)(sm + LNB_OFF);
    float* rS    = (float*)(sm + RS_OFF);
    float* rQ    = (float*)(sm + RQ_OFF);

    // stage depthwise weights + per-channel consts
    for (int i = t; i < 256 * 49; i += NT) dws[i] = dw_w[i];
    if (t < 256) {
        dwb_s[t] = dw_b[t];
        lnw_s[t] = ln_w[t];
        lnb_s[t] = ln_b[t];
    }

    // ---------------- depthwise conv 7x7 + stats (2 blocks, 128 positions) ----
    const int ci = t >> 7;            // 0..3
    const int p  = t & 127;           // 0..63 block A, 64..127 block B
    const int bs = p >> 6, pl = p & 63;
    const int pr = pl >> 3, pc = pl & 7;
    float sum = 0.f, ssq = 0.f;

    for (int st = 0; st < 16; st++) {
        const int c16 = st * 16;
        __syncthreads();
        // stage 16 channels x 2 blocks of 14x14 padded patches
        for (int id = t; id < 2 * 16 * 196; id += NT) {
            int pb  = id / 3136;
            int r2  = id - pb * 3136;
            int cc  = r2 / 196, rem = r2 % 196;
            int rr  = rem / 14, cw = rem % 14;
            int hh  = (pb ? h0B : h0A) - 3 + rr;
            int ww  = (pb ? w0B : w0A) - 3 + cw;
            const float* xb = pb ? xbB : xbA;
            float v = 0.f;
            if ((unsigned)hh < 56u && (unsigned)ww < 56u)
                v = xb[((c16 + cc) * HWD + hh) * HWD + ww];
            patch[((pb * 16 + cc) * 14 + rr) * 40 + cw] = v;
        }
        __syncthreads();
#pragma unroll
        for (int u = 0; u < 4; u++) {
            const int chl = ci + u * 4;       // 0..15 within stage
            const int ch  = c16 + chl;
            float a = dwb_s[ch];
            const float* w  = dws + ch * 49;
            const float* pp = patch + ((bs * 16 + chl) * 14 + pr) * 40 + pc;
#pragma unroll
            for (int kh = 0; kh < 7; kh++)
#pragma unroll
                for (int kw = 0; kw < 7; kw++)
                    a += pp[kh * 40 + kw] * w[kh * 7 + kw];
            sum += a;
            ssq += a * a;
            Ys[p * Y_STRIDE + ch] = __float2bfloat16(a);
        }
    }

    rS[ci * 128 + p] = sum;
    rQ[ci * 128 + p] = ssq;
    __syncthreads();
    {
        float S = rS[p] + rS[128 + p] + rS[256 + p] + rS[384 + p];
        float Q = rQ[p] + rQ[128 + p] + rQ[256 + p] + rQ[384 + p];
        float mu   = S * (1.f / 256.f);
        float var  = Q * (1.f / 256.f) - mu * mu;
        float rstd = rsqrtf(fmaxf(var, 0.f) + 1e-6f);
        for (int st = 0; st < 16; st++) {
#pragma unroll
            for (int u = 0; u < 4; u++) {
                int ch = st * 16 + ci + u * 4;
                float y = __bfloat162float(Ys[p * Y_STRIDE + ch]);
                y = (y - mu) * rstd * lnw_s[ch] + lnb_s[ch];
                Ys[p * Y_STRIDE + ch] = __float2bfloat16(y);
            }
        }
    }

    // zero Zacc (dws alias is dead now); ordered vs first rmw by chunk-loop barriers
    {
        unsigned* zz = (unsigned*)Zacc;
        for (int i = t; i < 128 * Z_STRIDE / 2; i += NT) zz[i] = 0u;
    }

    // ---------------- MLP: 16 chunks of N1=64; warps 8(M) x 2(N) ----------------
    __nv_bfloat16* W1c = (__nv_bfloat16*)(sm + W1C_OFF);
    __nv_bfloat16* W2c = (__nv_bfloat16*)(sm + W2C_OFF);
    __nv_bfloat16* Hcn = (__nv_bfloat16*)(sm + HC_OFF);
    const int lane = t & 31, wrp = t >> 5;
    const int wm = wrp & 7, wn = wrp >> 3;   // 8 (M) x 2 (N)
    const int m0 = wm * 16;
    const unsigned Ybase  = smem_u32(Ys);
    const unsigned W1base = smem_u32(W1c);
    const unsigned W2base = smem_u32(W2c);
    const unsigned Hbase  = smem_u32(Hcn);
    const unsigned aOffY = Ybase + (m0 + (lane & 15)) * (Y_STRIDE * 2) + ((lane >> 4) << 4);
    const unsigned aOffH = Hbase + (m0 + (lane & 15)) * (HC_STRIDE * 2) + ((lane >> 4) << 4);

    for (int nc = 0; nc < 16; nc++) {
        __syncthreads();  // prev GEMM2 + Zacc rmw done; safe to overwrite W/Hc
        {   // W1 chunk [256 x 64], W2 chunk [64 x 256]
            const uint4* s1 = (const uint4*)g_W1B;
            uint4*       d1 = (uint4*)W1c;
            for (int i = t; i < 2048; i += NT) {
                int k = i >> 3, q = i & 7;
                d1[k * 9 + q] = s1[k * 128 + nc * 8 + q];
            }
            const uint4* s2 = (const uint4*)g_W2B;
            uint4*       d2 = (uint4*)W2c;
            for (int i = t; i < 2048; i += NT) {
                int k = i >> 5, q = i & 31;
                d2[k * 33 + q] = s2[(nc * 64 + k) * 32 + q];
            }
            if (t < 64) b1c[t] = b1[nc * 64 + t];
        }
        __syncthreads();

        // GEMM1: H[128,64] = Y[128,256] @ W1c[256,64]; warp tile 16x32
        float acc1[4][4];
#pragma unroll
        for (int i = 0; i < 4; i++)
#pragma unroll
            for (int q = 0; q < 4; q++) acc1[i][q] = 0.f;

#pragma unroll 4
        for (int kk = 0; kk < 256; kk += 16) {
            unsigned a[4];
            ldsm4(a, aOffY + kk * 2);
#pragma unroll
            for (int q = 0; q < 2; q++) {
                unsigned bq[4];
                ldsm4t(bq, W1base + (kk + (lane & 15)) * (W1C_STRIDE * 2)
                                 + (wn * 32 + q * 16) * 2 + ((lane >> 4) << 4));
                mma16816(acc1[2 * q],     a, bq[0], bq[1]);
                mma16816(acc1[2 * q + 1], a, bq[2], bq[3]);
            }
        }

        // bias + GELU + pack bf16 into Hc
#pragma unroll
        for (int q = 0; q < 4; q++) {
            int c0 = wn * 32 + q * 8 + 2 * (lane & 3);
            int r  = m0 + (lane >> 2);
            float f0 = gelu_f(acc1[q][0] + b1c[c0]);
            float f1 = gelu_f(acc1[q][1] + b1c[c0 + 1]);
            float f2 = gelu_f(acc1[q][2] + b1c[c0]);
            float f3 = gelu_f(acc1[q][3] + b1c[c0 + 1]);
            __nv_bfloat162 h01, h23;
            h01.x = __float2bfloat16(f0); h01.y = __float2bfloat16(f1);
            h23.x = __float2bfloat16(f2); h23.y = __float2bfloat16(f3);
            *(__nv_bfloat162*)&Hcn[r * HC_STRIDE + c0]       = h01;
            *(__nv_bfloat162*)&Hcn[(r + 8) * HC_STRIDE + c0] = h23;
        }
        __syncthreads();

        // GEMM2: Zp[128,256] = H[128,64] @ W2c[64,256]; warp tile 16x128
        float accZ[16][4];
#pragma unroll
        for (int i = 0; i < 16; i++)
#pragma unroll
            for (int q = 0; q < 4; q++) accZ[i][q] = 0.f;

#pragma unroll
        for (int kk = 0; kk < 64; kk += 16) {
            unsigned a[4];
            ldsm4(a, aOffH + kk * 2);
#pragma unroll
            for (int q = 0; q < 8; q++) {
                unsigned bq[4];
                ldsm4t(bq, W2base + (kk + (lane & 15)) * (W2C_STRIDE * 2)
                                 + (wn * 128 + q * 16) * 2 + ((lane >> 4) << 4));
                mma16816(accZ[2 * q],     a, bq[0], bq[1]);
                mma16816(accZ[2 * q + 1], a, bq[2], bq[3]);
            }
        }

        // accumulate into Zacc (bf16); each warp owns disjoint rows/cols
#pragma unroll
        for (int q = 0; q < 16; q++) {
            int c0 = wn * 128 + q * 8 + 2 * (lane & 3);
            int r  = m0 + (lane >> 2);
            __nv_bfloat162* z0 = (__nv_bfloat162*)&Zacc[r * Z_STRIDE + c0];
            __nv_bfloat162* z1 = (__nv_bfloat162*)&Zacc[(r + 8) * Z_STRIDE + c0];
            float2 v0 = __bfloat1622float2(*z0);
            float2 v1 = __bfloat1622float2(*z1);
            v0.x += accZ[q][0]; v0.y += accZ[q][1];
            v1.x += accZ[q][2]; v1.y += accZ[q][3];
            *z0 = __float22bfloat162_rn(v0);
            *z1 = __float22bfloat162_rn(v1);
        }
    }
    __syncthreads();

    // epilogue: out = x + (z + b2) * gamma  (both blocks active)
    for (int i = t; i < 8192; i += NT) {
        int pb  = i >> 12;                 // 0 = block A, 1 = block B
        if (pb && !hasB) continue;
        int jj  = i & 4095;
        int c   = jj >> 4, sub = jj & 15;
        int rr  = sub >> 1, half = sub & 1;
        int p0  = pb * 64 + rr * 8 + half * 4;
        float gm = __ldg(gamma + c), bb = __ldg(b2 + c);
        float4 z4;
        z4.x = (__bfloat162float(Zacc[(p0 + 0) * Z_STRIDE + c]) + bb) * gm;
        z4.y = (__bfloat162float(Zacc[(p0 + 1) * Z_STRIDE + c]) + bb) * gm;
        z4.z = (__bfloat162float(Zacc[(p0 + 2) * Z_STRIDE + c]) + bb) * gm;
        z4.w = (__bfloat162float(Zacc[(p0 + 3) * Z_STRIDE + c]) + bb) * gm;
        const float* xb = pb ? xbB : xbA;
        float*       ob = pb ? obB : obA;
        int h0 = pb ? h0B : h0A, w0 = pb ? w0B : w0A;
        size_t g = (size_t)(c * HWD + h0 + rr) * HWD + w0;
        float4 xv = ((const float4*)(xb + g))[half];
        xv.x += z4.x; xv.y += z4.y; xv.z += z4.z; xv.w += z4.w;
        ((float4*)(ob + g))[half] = xv;
    }
}

extern "C" void kernel_launch(void* const* d_in, const int* in_sizes, int n_in,
                              void* d_out, int out_size) {
    const float* x     = (const float*)d_in[0];
    const int*   mask  = (const int*)d_in[1];
    const float* dw_w  = (const float*)d_in[2];
    const float* dw_b  = (const float*)d_in[3];
    const float* ln_w  = (const float*)d_in[4];
    const float* ln_b  = (const float*)d_in[5];
    const float* w1    = (const float*)d_in[6];
    const float* b1    = (const float*)d_in[7];
    const float* w2    = (const float*)d_in[8];
    const float* b2    = (const float*)d_in[9];
    const float* gamma = (const float*)d_in[10];
    float* out = (float*)d_out;

    convert_weights<<<512, 512>>>(w1, w2);
    build_lists<<<(NBLK + 255) / 256, 256>>>(mask);
    copy_kernel<<<NBLK, 256>>>(x, mask, out);

    cudaFuncSetAttribute(block_kernel,
                         cudaFuncAttributeMaxDynamicSharedMemorySize, SMEM_TOTAL);
    block_kernel<<<NBLK / 2, NT, SMEM_TOTAL>>>(x, dw_w, dw_b, ln_w, ln_b,
                                               b1, b2, gamma, out);
}

// round 10
// speedup vs baseline: 1.6753x; 1.6753x over previous
#include <cuda_runtime.h>
#include <cuda_bf16.h>

#define DIMC 256
#define HWD  56
#define NBLK 1568   // 32 images * 49 spatial blocks
#define NT   512    // threads per CTA (16 warps)

// ---------------- device weight scratch (bf16) ----------------
__device__ __align__(16) __nv_bfloat16 g_W1B[256 * 1024]; // [K=256][N=1024]
__device__ __align__(16) __nv_bfloat16 g_W2B[1024 * 256]; // [K=1024][N=256]

__global__ void convert_weights(const float* __restrict__ w1,
                                const float* __restrict__ w2) {
    int id = blockIdx.x * blockDim.x + threadIdx.x;
    if (id < 256 * 1024) {
        g_W1B[id] = __float2bfloat16(w1[id]);
        g_W2B[id] = __float2bfloat16(w2[id]);
    }
}

// ---------------- smem layout (bytes) ----------------
// Y    : bf16 [64][264] = 33792
// W1c  : bf16 [256][136] = 69632   (aliases: patch f32 2 x 16x14x37 = 66304; zs f32 64x261)
// W2c  : bf16 [128][264] = 67584   (alias: dws f32 256*49 = 50176)
// Hc   : bf16 [64][136]  = 17408
#define Y_OFF      0
#define Y_STRIDE   264
#define W1C_OFF    33792
#define W1C_STRIDE 136
#define W2C_OFF    103424
#define W2C_STRIDE 264
#define HC_OFF     171008
#define HC_STRIDE  136
#define B1C_OFF    188416
#define DWB_OFF    188928
#define LNW_OFF    189952
#define LNB_OFF    190976
#define RS_OFF     192000   // 16 warps x 64 pos f32 = 4096
#define RQ_OFF     196096   // 4096
#define SMEM_TOTAL 200192

#define PATCH_BYTES 33152   // 16 ch * 14 rows * 37 cols * 4B
#define PATCH_FLOATS 8288

__device__ __forceinline__ unsigned smem_u32(const void* p) {
    return (unsigned)__cvta_generic_to_shared(p);
}
__device__ __forceinline__ void cp4z(unsigned dst, const void* src, int sz) {
    asm volatile("cp.async.ca.shared.global [%0], [%1], 4, %2;"
                 :: "r"(dst), "l"(src), "r"(sz));
}
__device__ __forceinline__ void cp16(unsigned dst, const void* src) {
    asm volatile("cp.async.cg.shared.global [%0], [%1], 16;"
                 :: "r"(dst), "l"(src));
}
#define CP_COMMIT() asm volatile("cp.async.commit_group;" ::: "memory")
#define CP_WAIT(n)  asm volatile("cp.async.wait_group %0;" :: "n"(n) : "memory")

__device__ __forceinline__ void ldsm4(unsigned r[4], unsigned addr) {
    asm volatile("ldmatrix.sync.aligned.m8n8.x4.shared.b16 {%0,%1,%2,%3}, [%4];"
                 : "=r"(r[0]), "=r"(r[1]), "=r"(r[2]), "=r"(r[3]) : "r"(addr));
}
__device__ __forceinline__ void ldsm4t(unsigned r[4], unsigned addr) {
    asm volatile("ldmatrix.sync.aligned.m8n8.x4.trans.shared.b16 {%0,%1,%2,%3}, [%4];"
                 : "=r"(r[0]), "=r"(r[1]), "=r"(r[2]), "=r"(r[3]) : "r"(addr));
}
__device__ __forceinline__ void mma16816(float d[4], const unsigned a[4],
                                         unsigned b0, unsigned b1) {
    asm volatile(
        "mma.sync.aligned.m16n8k16.row.col.f32.bf16.bf16.f32 "
        "{%0,%1,%2,%3}, {%4,%5,%6,%7}, {%8,%9}, {%0,%1,%2,%3};"
        : "+f"(d[0]), "+f"(d[1]), "+f"(d[2]), "+f"(d[3])
        : "r"(a[0]), "r"(a[1]), "r"(a[2]), "r"(a[3]), "r"(b0), "r"(b1));
}
__device__ __forceinline__ float gelu_f(float v) {
    float u = 0.7978845608028654f * (v + 0.044715f * v * v * v);
    float th;
    asm("tanh.approx.f32 %0, %1;" : "=f"(th) : "f"(u));
    return 0.5f * v * (1.0f + th);
}

__global__ __launch_bounds__(NT, 1)
void block_kernel(const float* __restrict__ x, const int* __restrict__ mask,
                  const float* __restrict__ dw_w, const float* __restrict__ dw_b,
                  const float* __restrict__ ln_w, const float* __restrict__ ln_b,
                  const float* __restrict__ b1, const float* __restrict__ b2,
                  const float* __restrict__ gamma, float* __restrict__ out) {
    extern __shared__ char sm[];
    const int t   = threadIdx.x;
    const int blk = blockIdx.x;
    const int b   = blk / 49;
    const int s   = blk % 49;
    const int h0  = (s / 7) * 8;
    const int w0  = (s % 7) * 8;
    const float* xb = x   + (size_t)b * DIMC * HWD * HWD;
    float*       ob = out + (size_t)b * DIMC * HWD * HWD;

    if (mask[blk] == 0) {
        for (int i = t; i < 4096; i += NT) {
            int c = i >> 4, sub = i & 15;
            int rr = sub >> 1, half = sub & 1;
            size_t g = (size_t)(c * HWD + h0 + rr) * HWD + w0;
            ((float4*)(ob + g))[half] = ((const float4*)(xb + g))[half];
        }
        return;
    }

    __nv_bfloat16* Ys = (__nv_bfloat16*)(sm + Y_OFF);
    float* patchF = (float*)(sm + W1C_OFF);   // 2 buffers of 16x14x37 f32
    float* dws    = (float*)(sm + W2C_OFF);   // 256*49 f32 (conv phase only)
    float* b1c    = (float*)(sm + B1C_OFF);
    float* dwb_s  = (float*)(sm + DWB_OFF);
    float* lnw_s  = (float*)(sm + LNW_OFF);
    float* lnb_s  = (float*)(sm + LNB_OFF);
    float* rS     = (float*)(sm + RS_OFF);
    float* rQ     = (float*)(sm + RQ_OFF);

    const int lane = t & 31, wrp = t >> 5;

    // -------- prologue: async-stage dw weights + patch(0); plain consts ------
    const unsigned dwsBase   = smem_u32(dws);
    const unsigned patchBase = smem_u32(patchF);
    {
        const uint4* src = (const uint4*)dw_w;   // 3136 uint4
        for (int i = t; i < 3136; i += NT)
            cp16(dwsBase + i * 16, src + i);
        if (t < 256) {
            dwb_s[t] = dw_b[t];
            lnw_s[t] = ln_w[t];
            lnb_s[t] = ln_b[t];
        }
    }
    // patch staging: warp stages its own channel (ch = wrp) of the stage
    const float* xch0 = xb + (size_t)wrp * (HWD * HWD);   // channel wrp plane
    {
        unsigned pb = patchBase + (wrp * 14) * 37 * 4;    // buf 0
        const float* xsrc = xch0;                          // stage 0: channels 0..15
#pragma unroll
        for (int k = 0; k < 7; k++) {
            int pos = lane + k * 32;
            if (pos < 196) {
                int rr = pos / 14, cw = pos - rr * 14;
                int hh = h0 - 3 + rr, ww = w0 - 3 + cw;
                bool ok = ((unsigned)hh < 56u) && ((unsigned)ww < 56u);
                const float* srcp = ok ? (xsrc + hh * HWD + ww) : xsrc;
                cp4z(pb + (rr * 37 + cw) * 4, srcp, ok ? 4 : 0);
            }
        }
    }
    CP_COMMIT();

    // -------- conv: 16 stages, warp=channel, thread=(row, colpair) ----------
    const int row = lane >> 2;          // 0..7
    const int c0  = (lane & 3) * 2;     // 0,2,4,6
    const int p0  = row * 8 + c0;
    float sum0 = 0.f, ssq0 = 0.f, sum1 = 0.f, ssq1 = 0.f;

    for (int st = 0; st < 16; st++) {
        __syncthreads();   // compute(st-1) fully done -> safe to refill its buffer
        if (st < 15) {
            unsigned pb = patchBase + ((st + 1) & 1) * PATCH_BYTES
                        + (wrp * 14) * 37 * 4;
            const float* xsrc = xch0 + (size_t)(st + 1) * 16 * (HWD * HWD);
#pragma unroll
            for (int k = 0; k < 7; k++) {
                int pos = lane + k * 32;
                if (pos < 196) {
                    int rr = pos / 14, cw = pos - rr * 14;
                    int hh = h0 - 3 + rr, ww = w0 - 3 + cw;
                    bool ok = ((unsigned)hh < 56u) && ((unsigned)ww < 56u);
                    const float* srcp = ok ? (xsrc + hh * HWD + ww) : xsrc;
                    cp4z(pb + (rr * 37 + cw) * 4, srcp, ok ? 4 : 0);
                }
            }
            CP_COMMIT();
            CP_WAIT(1);    // patch(st) ready; patch(st+1) in flight
        } else {
            CP_WAIT(0);
        }
        __syncthreads();

        const int chg = st * 16 + wrp;
        const float* w   = dws + chg * 49;
        const float* pch = patchF + (st & 1) * PATCH_FLOATS + (wrp * 14) * 37;
        float o0 = 0.f, o1 = 0.f;
#pragma unroll
        for (int kh = 0; kh < 7; kh++) {
            const float* pr = pch + (row + kh) * 37 + c0;
            float v0 = pr[0], v1 = pr[1], v2 = pr[2], v3 = pr[3];
            float v4 = pr[4], v5 = pr[5], v6 = pr[6], v7 = pr[7];
            float w0v = w[kh * 7 + 0], w1v = w[kh * 7 + 1], w2v = w[kh * 7 + 2];
            float w3v = w[kh * 7 + 3], w4v = w[kh * 7 + 4], w5v = w[kh * 7 + 5];
            float w6v = w[kh * 7 + 6];
            o0 += v0 * w0v; o1 += v1 * w0v;
            o0 += v1 * w1v; o1 += v2 * w1v;
            o0 += v2 * w2v; o1 += v3 * w2v;
            o0 += v3 * w3v; o1 += v4 * w3v;
            o0 += v4 * w4v; o1 += v5 * w4v;
            o0 += v5 * w5v; o1 += v6 * w5v;
            o0 += v6 * w6v; o1 += v7 * w6v;
        }
        float bias = dwb_s[chg];
        o0 += bias; o1 += bias;
        sum0 += o0; ssq0 += o0 * o0;
        sum1 += o1; ssq1 += o1 * o1;
        Ys[p0 * Y_STRIDE + chg]       = __float2bfloat16(o0);
        Ys[(p0 + 1) * Y_STRIDE + chg] = __float2bfloat16(o1);
    }

    rS[wrp * 64 + p0]     = sum0;
    rS[wrp * 64 + p0 + 1] = sum1;
    rQ[wrp * 64 + p0]     = ssq0;
    rQ[wrp * 64 + p0 + 1] = ssq1;
    __syncthreads();

    // -------- LayerNorm (thread owns 16 channels x 2 positions) -------------
    {
        float S0 = 0.f, Q0 = 0.f, S1 = 0.f, Q1 = 0.f;
#pragma unroll
        for (int wq = 0; wq < 16; wq++) {
            S0 += rS[wq * 64 + p0];     Q0 += rQ[wq * 64 + p0];
            S1 += rS[wq * 64 + p0 + 1]; Q1 += rQ[wq * 64 + p0 + 1];
        }
        float mu0 = S0 * (1.f / 256.f);
        float mu1 = S1 * (1.f / 256.f);
        float rstd0 = rsqrtf(fmaxf(Q0 * (1.f / 256.f) - mu0 * mu0, 0.f) + 1e-6f);
        float rstd1 = rsqrtf(fmaxf(Q1 * (1.f / 256.f) - mu1 * mu1, 0.f) + 1e-6f);
#pragma unroll 4
        for (int st = 0; st < 16; st++) {
            int ch = st * 16 + wrp;
            float lw = lnw_s[ch], lb = lnb_s[ch];
            float y0 = __bfloat162float(Ys[p0 * Y_STRIDE + ch]);
            float y1 = __bfloat162float(Ys[(p0 + 1) * Y_STRIDE + ch]);
            y0 = (y0 - mu0) * rstd0 * lw + lb;
            y1 = (y1 - mu1) * rstd1 * lw + lb;
            Ys[p0 * Y_STRIDE + ch]       = __float2bfloat16(y0);
            Ys[(p0 + 1) * Y_STRIDE + ch] = __float2bfloat16(y1);
        }
    }

    // ---------------- MLP via mma.sync bf16 (16 warps: 4M x 4N) -------------
    __nv_bfloat16* W1c = (__nv_bfloat16*)(sm + W1C_OFF);
    __nv_bfloat16* W2c = (__nv_bfloat16*)(sm + W2C_OFF);
    __nv_bfloat16* Hcn = (__nv_bfloat16*)(sm + HC_OFF);
    const int wm = wrp & 3, wn = wrp >> 2;   // 4 (M) x 4 (N)
    const int m0 = wm * 16;
    const unsigned Ybase  = smem_u32(Ys);
    const unsigned W1base = smem_u32(W1c);
    const unsigned W2base = smem_u32(W2c);
    const unsigned Hbase  = smem_u32(Hcn);
    const unsigned aOffY = Ybase + (m0 + (lane & 15)) * (Y_STRIDE * 2) + ((lane >> 4) << 4);
    const unsigned aOffH = Hbase + (m0 + (lane & 15)) * (HC_STRIDE * 2) + ((lane >> 4) << 4);

    float accZ[8][4];
#pragma unroll
    for (int i = 0; i < 8; i++)
#pragma unroll
        for (int q = 0; q < 4; q++) accZ[i][q] = 0.f;

    for (int nc = 0; nc < 8; nc++) {
        __syncthreads();  // prev GEMM2 done reading W2c/Hc
        {   // async-stage W1 chunk [256x128] and W2 chunk [128x256]
            const uint4* s1 = (const uint4*)g_W1B;
            for (int i = t; i < 4096; i += NT) {
                int k = i >> 4, q = i & 15;
                cp16(W1base + (k * 17 + q) * 16, s1 + k * 128 + nc * 16 + q);
            }
            const uint4* s2 = (const uint4*)g_W2B;
            for (int i = t; i < 4096; i += NT) {
                int k = i >> 5, q = i & 31;
                cp16(W2base + (k * 33 + q) * 16, s2 + (size_t)(nc * 128 + k) * 32 + q);
            }
            if (t < 128) b1c[t] = b1[nc * 128 + t];
            CP_COMMIT();
            CP_WAIT(0);
        }
        __syncthreads();

        // GEMM1: H[64,128] = Y[64,256] @ W1c[256,128]; warp tile 16x32
        float acc1[4][4];
#pragma unroll
        for (int i = 0; i < 4; i++)
#pragma unroll
            for (int q = 0; q < 4; q++) acc1[i][q] = 0.f;

#pragma unroll 4
        for (int kk = 0; kk < 256; kk += 16) {
            unsigned a[4];
            ldsm4(a, aOffY + kk * 2);
#pragma unroll
            for (int q = 0; q < 2; q++) {
                unsigned bq[4];
                ldsm4t(bq, W1base + (kk + (lane & 15)) * (W1C_STRIDE * 2)
                                 + (wn * 32 + q * 16) * 2 + ((lane >> 4) << 4));
                mma16816(acc1[2 * q],     a, bq[0], bq[1]);
                mma16816(acc1[2 * q + 1], a, bq[2], bq[3]);
            }
        }

        // bias + GELU + pack bf16 into Hc
#pragma unroll
        for (int q = 0; q < 4; q++) {
            int cc0 = wn * 32 + q * 8 + 2 * (lane & 3);
            int r   = m0 + (lane >> 2);
            float f0 = gelu_f(acc1[q][0] + b1c[cc0]);
            float f1 = gelu_f(acc1[q][1] + b1c[cc0 + 1]);
            float f2 = gelu_f(acc1[q][2] + b1c[cc0]);
            float f3 = gelu_f(acc1[q][3] + b1c[cc0 + 1]);
            __nv_bfloat162 h01, h23;
            h01.x = __float2bfloat16(f0); h01.y = __float2bfloat16(f1);
            h23.x = __float2bfloat16(f2); h23.y = __float2bfloat16(f3);
            *(__nv_bfloat162*)&Hcn[r * HC_STRIDE + cc0]       = h01;
            *(__nv_bfloat162*)&Hcn[(r + 8) * HC_STRIDE + cc0] = h23;
        }
        __syncthreads();

        // GEMM2: Z[64,256] += H[64,128] @ W2c[128,256]; warp tile 16x64
#pragma unroll 2
        for (int kk = 0; kk < 128; kk += 16) {
            unsigned a[4];
            ldsm4(a, aOffH + kk * 2);
#pragma unroll
            for (int q = 0; q < 4; q++) {
                unsigned bq[4];
                ldsm4t(bq, W2base + (kk + (lane & 15)) * (W2C_STRIDE * 2)
                                 + (wn * 64 + q * 16) * 2 + ((lane >> 4) << 4));
                mma16816(accZ[2 * q],     a, bq[0], bq[1]);
                mma16816(accZ[2 * q + 1], a, bq[2], bq[3]);
            }
        }
    }
    __syncthreads();

    // dump Z to smem (transpose buffer, stride 261)
    float* zs = (float*)(sm + W1C_OFF);
#pragma unroll
    for (int q = 0; q < 8; q++) {
        int cc0 = wn * 64 + q * 8 + 2 * (lane & 3);
        int r   = m0 + (lane >> 2);
        zs[r * 261 + cc0]           = accZ[q][0];
        zs[r * 261 + cc0 + 1]       = accZ[q][1];
        zs[(r + 8) * 261 + cc0]     = accZ[q][2];
        zs[(r + 8) * 261 + cc0 + 1] = accZ[q][3];
    }
    __syncthreads();

    // epilogue: out = x + (z + b2) * gamma, float4-vectorized
    for (int i = t; i < 4096; i += NT) {
        int c = i >> 4, sub = i & 15;
        int rr = sub >> 1, half = sub & 1;
        int pp = rr * 8 + half * 4;
        float gm = __ldg(gamma + c), bb = __ldg(b2 + c);
        float4 z4;
        z4.x = (zs[(pp + 0) * 261 + c] + bb) * gm;
        z4.y = (zs[(pp + 1) * 261 + c] + bb) * gm;
        z4.z = (zs[(pp + 2) * 261 + c] + bb) * gm;
        z4.w = (zs[(pp + 3) * 261 + c] + bb) * gm;
        size_t g = (size_t)(c * HWD + h0 + rr) * HWD + w0;
        float4 xv = ((const float4*)(xb + g))[half];
        xv.x += z4.x; xv.y += z4.y; xv.z += z4.z; xv.w += z4.w;
        ((float4*)(ob + g))[half] = xv;
    }
}

extern "C" void kernel_launch(void* const* d_in, const int* in_sizes, int n_in,
                              void* d_out, int out_size) {
    const float* x     = (const float*)d_in[0];
    const int*   mask  = (const int*)d_in[1];
    const float* dw_w  = (const float*)d_in[2];
    const float* dw_b  = (const float*)d_in[3];
    const float* ln_w  = (const float*)d_in[4];
    const float* ln_b  = (const float*)d_in[5];
    const float* w1    = (const float*)d_in[6];
    const float* b1    = (const float*)d_in[7];
    const float* w2    = (const float*)d_in[8];
    const float* b2    = (const float*)d_in[9];
    const float* gamma = (const float*)d_in[10];
    float* out = (float*)d_out;

    convert_weights<<<512, 512>>>(w1, w2);

    cudaFuncSetAttribute(block_kernel,
                         cudaFuncAttributeMaxDynamicSharedMemorySize, SMEM_TOTAL);
    block_kernel<<<NBLK, NT, SMEM_TOTAL>>>(x, mask, dw_w, dw_b, ln_w, ln_b,
                                           b1, b2, gamma, out);
}